// round 14
// baseline (speedup 1.0000x reference)
#include <cuda_runtime.h>
#include <cuda_bf16.h>
#include <cuda_fp16.h>

#define N_NODES 50000
#define N_EDGES 800000
#define FEAT 10
#define HID 64
#define N_SHEETS 256
#define SHEET_LEN 128

#define SCAN_BLK 512
#define SCAN_GRID ((N_NODES + SCAN_BLK - 1) / SCAN_BLK)   // 98

// ---------------- scratch (static device globals; no allocation) ----------------
__device__ __align__(16) float d_hA[N_NODES * HID];   // fp16 rows live here (cast)
__device__ __align__(16) float d_hB[N_NODES * HID];   // fp32 final h3 (tail gathers it)
__device__ int   d_deg[N_NODES];
__device__ float d_dinv[N_NODES];
__device__ int   d_rowptr[N_NODES + 1];
__device__ int   d_rowcur[N_NODES];
__device__ __align__(16) int2 d_csr[N_EDGES];         // {src, weight-as-int}
__device__ int   d_part[SCAN_GRID + 32];
__device__ float d_gsum[HID];
__device__ __align__(16) __half2 d_g2[N_NODES * 32];  // fp16 intermediate rows
__device__ __align__(16) __half2 d_g3[N_NODES * 32];

// ---------------- CSR build ----------------

__global__ void zero_kernel(int* deg, float* gsum, int n) {
    int i = blockIdx.x * blockDim.x + threadIdx.x;
    if (i < n) deg[i] = 0;
    if (i < HID) gsum[i] = 0.f;
}

__global__ void deg_kernel(const int* __restrict__ dst, int* __restrict__ deg, int nE) {
    int e = blockIdx.x * blockDim.x + threadIdx.x;
    if (e < nE) atomicAdd(&deg[dst[e]], 1);
}

// pass 1: per-block sums of deg, plus dinv (reads deg anyway)
__global__ void scan1_kernel(const int* __restrict__ deg, float* __restrict__ dinv,
                             int* __restrict__ partials, int n) {
    __shared__ int ws[SCAN_BLK / 32];
    int i = blockIdx.x * blockDim.x + threadIdx.x;
    int lane = threadIdx.x & 31, wrp = threadIdx.x >> 5;
    int v = (i < n) ? deg[i] : 0;
    if (i < n) dinv[i] = rsqrtf((float)v + 1.0f);
    int s = v;
    #pragma unroll
    for (int off = 16; off; off >>= 1) s += __shfl_down_sync(0xffffffffu, s, off);
    if (lane == 0) ws[wrp] = s;
    __syncthreads();
    if (wrp == 0) {
        int t = (lane < SCAN_BLK / 32) ? ws[lane] : 0;
        #pragma unroll
        for (int off = 16; off; off >>= 1) t += __shfl_down_sync(0xffffffffu, t, off);
        if (lane == 0) partials[blockIdx.x] = t;
    }
}

// pass 2 (merged): per-block rescan; warp 1 concurrently sums partials[0..bid-1]
__global__ void scan3_kernel(const int* __restrict__ deg, const int* __restrict__ partials,
                             int* __restrict__ row_ptr, int* __restrict__ row_cur, int n) {
    __shared__ int ws[SCAN_BLK / 32];
    __shared__ int s_base;
    int i = blockIdx.x * blockDim.x + threadIdx.x;
    int lane = threadIdx.x & 31, wrp = threadIdx.x >> 5;
    int v = (i < n) ? deg[i] : 0;
    int x = v;
    #pragma unroll
    for (int off = 1; off < 32; off <<= 1) {
        int y = __shfl_up_sync(0xffffffffu, x, off);
        if (lane >= off) x += y;
    }
    if (lane == 31) ws[wrp] = x;
    __syncthreads();
    if (wrp == 0) {
        int y = (lane < SCAN_BLK / 32) ? ws[lane] : 0;
        #pragma unroll
        for (int off = 1; off < 16; off <<= 1) {
            int z = __shfl_up_sync(0xffffffffu, y, off);
            if (lane >= off) y += z;
        }
        if (lane < SCAN_BLK / 32) ws[lane] = y;
    } else if (wrp == 1) {
        int pre = 0;
        for (int bp = 0; bp < SCAN_GRID; bp += 32) {
            int idx = bp + lane;
            int pv = (idx < SCAN_GRID && idx < blockIdx.x) ? partials[idx] : 0;
            #pragma unroll
            for (int off = 16; off; off >>= 1) pv += __shfl_down_sync(0xffffffffu, pv, off);
            if (lane == 0) pre += pv;
        }
        if (lane == 0) s_base = pre;
    }
    __syncthreads();
    int excl = x - v + (wrp > 0 ? ws[wrp - 1] : 0) + s_base;
    if (i < n) { row_ptr[i] = excl; row_cur[i] = excl; }
    if (i == n - 1) row_ptr[n] = excl + v;
}

// scatter with fused edge weight, packed {src, w}
__global__ void scatter_kernel(const int* __restrict__ src, const int* __restrict__ dst,
                               const float* __restrict__ dinv,
                               int* __restrict__ rowcur, int2* __restrict__ csr, int nE) {
    int e = blockIdx.x * blockDim.x + threadIdx.x;
    if (e >= nE) return;
    int d = dst[e];
    int s = src[e];
    int p = atomicAdd(&rowcur[d], 1);
    csr[p] = make_int2(s, __float_as_int(dinv[s] * dinv[d]));
}

// ---------------- fused layer kernels (all warp-local: gather -> shuffle-GEMM) ----------------
// Register layout: within a warp, lane l owns features (2l, 2l+1) of its node's row.

// Kernel A: t0 = agg(x) [10-wide]; g2 = relu(t0·W1 + b1)·W2  -> fp16 rows
__global__ void __launch_bounds__(256)
layerA_kernel(const float* __restrict__ X, const int* __restrict__ row_ptr,
              const int2* __restrict__ csr, const float* __restrict__ dinv,
              const float* __restrict__ W1, const float* __restrict__ b1,
              const float* __restrict__ W2, __half2* __restrict__ Gout, int n) {
    __shared__ __align__(16) float2 W1p[FEAT][32];   // row k as 32 (even,odd) pairs
    __shared__ __align__(16) float2 W2p[HID][32];
    __shared__ float2 b1p[32];
    int tid = threadIdx.x;
    for (int i = tid; i < FEAT * 32; i += 256) ((float2*)W1p)[i] = ((const float2*)W1)[i];
    for (int i = tid; i < HID * 32; i += 256)  ((float2*)W2p)[i] = ((const float2*)W2)[i];
    if (tid < 32) b1p[tid] = ((const float2*)b1)[tid];
    __syncthreads();

    int warp = (blockIdx.x * blockDim.x + tid) >> 5;
    int lane = tid & 31;
    if (warp >= n) return;

    // gather phase: t0[lane] for lane<10
    int beg = row_ptr[warp], end = row_ptr[warp + 1];
    float acc = 0.f;
    for (int e = beg; e < end; e++) {
        int2 sw = csr[e];                          // warp-uniform 8B
        float w = __int_as_float(sw.y);
        if (lane < FEAT)
            acc = fmaf(w, X[(size_t)sw.x * FEAT + lane], acc);
    }
    if (lane < FEAT) {
        float di = dinv[warp];
        acc = fmaf(di * di, X[(size_t)warp * FEAT + lane], acc);
    }

    // gemm1: h[2l], h[2l+1]
    float2 bb = b1p[lane];
    float h0 = bb.x, h1 = bb.y;
    #pragma unroll
    for (int k = 0; k < FEAT; k++) {
        float tk = __shfl_sync(0xffffffffu, acc, k);
        float2 w = W1p[k][lane];
        h0 = fmaf(tk, w.x, h0);
        h1 = fmaf(tk, w.y, h1);
    }
    h0 = fmaxf(h0, 0.f);
    h1 = fmaxf(h1, 0.f);

    // gemm2: g[2l], g[2l+1]
    float g0 = 0.f, g1 = 0.f;
    #pragma unroll
    for (int m = 0; m < 32; m++) {
        float hk0 = __shfl_sync(0xffffffffu, h0, m);   // feature 2m
        float hk1 = __shfl_sync(0xffffffffu, h1, m);   // feature 2m+1
        float2 wa = W2p[2 * m][lane];
        float2 wb = W2p[2 * m + 1][lane];
        g0 = fmaf(hk0, wa.x, g0); g1 = fmaf(hk0, wa.y, g1);
        g0 = fmaf(hk1, wb.x, g0); g1 = fmaf(hk1, wb.y, g1);
    }
    Gout[(size_t)warp * 32 + lane] = __floats2half2_rn(g0, g1);
}

// Kernel B: h2 = relu(agg(g2) + b2);  g3 = h2·W3  -> fp16 rows
__global__ void __launch_bounds__(256)
layerB_kernel(const __half2* __restrict__ G2, const int* __restrict__ row_ptr,
              const int2* __restrict__ csr, const float* __restrict__ dinv,
              const float* __restrict__ b2, const float* __restrict__ W3,
              __half2* __restrict__ Gout, int n) {
    __shared__ __align__(16) float2 W3p[HID][32];
    __shared__ float2 b2p[32];
    int tid = threadIdx.x;
    for (int i = tid; i < HID * 32; i += 256) ((float2*)W3p)[i] = ((const float2*)W3)[i];
    if (tid < 32) b2p[tid] = ((const float2*)b2)[tid];
    __syncthreads();

    int warp = (blockIdx.x * blockDim.x + tid) >> 5;
    int lane = tid & 31;
    if (warp >= n) return;

    int beg = row_ptr[warp], end = row_ptr[warp + 1];
    float a0 = 0.f, a1 = 0.f;
    for (int e = beg; e < end; e++) {
        int2 sw = csr[e];
        float w = __int_as_float(sw.y);
        float2 f = __half22float2(G2[(size_t)sw.x * 32 + lane]);   // 128B coalesced
        a0 = fmaf(w, f.x, a0);
        a1 = fmaf(w, f.y, a1);
    }
    float di = dinv[warp];
    float d2 = di * di;
    float2 fs = __half22float2(G2[(size_t)warp * 32 + lane]);
    float2 bb = b2p[lane];
    float h0 = fmaxf(fmaf(d2, fs.x, a0) + bb.x, 0.f);
    float h1 = fmaxf(fmaf(d2, fs.y, a1) + bb.y, 0.f);

    // gemm3
    float g0 = 0.f, g1 = 0.f;
    #pragma unroll
    for (int m = 0; m < 32; m++) {
        float hk0 = __shfl_sync(0xffffffffu, h0, m);
        float hk1 = __shfl_sync(0xffffffffu, h1, m);
        float2 wa = W3p[2 * m][lane];
        float2 wb = W3p[2 * m + 1][lane];
        g0 = fmaf(hk0, wa.x, g0); g1 = fmaf(hk0, wa.y, g1);
        g0 = fmaf(hk1, wb.x, g0); g1 = fmaf(hk1, wb.y, g1);
    }
    Gout[(size_t)warp * 32 + lane] = __floats2half2_rn(g0, g1);
}

// Kernel C: h3 = relu(agg(g3) + b3) -> fp32 rows; fused global-mean partial sums.
__global__ void __launch_bounds__(256)
layerC_kernel(const __half2* __restrict__ G3, const int* __restrict__ row_ptr,
              const int2* __restrict__ csr, const float* __restrict__ dinv,
              const float* __restrict__ b3,
              float2* __restrict__ Hout, float* __restrict__ gsum, int n) {
    __shared__ float2 sred[256];
    __shared__ float2 b3p[32];
    int tid = threadIdx.x;
    if (tid < 32) b3p[tid] = ((const float2*)b3)[tid];
    __syncthreads();

    int warp = (blockIdx.x * blockDim.x + tid) >> 5;
    int lane = tid & 31;
    int wrp = tid >> 5;

    float r0 = 0.f, r1 = 0.f;
    if (warp < n) {
        int beg = row_ptr[warp], end = row_ptr[warp + 1];
        float a0 = 0.f, a1 = 0.f;
        for (int e = beg; e < end; e++) {
            int2 sw = csr[e];
            float w = __int_as_float(sw.y);
            float2 f = __half22float2(G3[(size_t)sw.x * 32 + lane]);
            a0 = fmaf(w, f.x, a0);
            a1 = fmaf(w, f.y, a1);
        }
        float di = dinv[warp];
        float d2 = di * di;
        float2 fs = __half22float2(G3[(size_t)warp * 32 + lane]);
        float2 bb = b3p[lane];
        r0 = fmaxf(fmaf(d2, fs.x, a0) + bb.x, 0.f);
        r1 = fmaxf(fmaf(d2, fs.y, a1) + bb.y, 0.f);
        Hout[(size_t)warp * 32 + lane] = make_float2(r0, r1);
    }

    // fused global-sum: block reduce 8 nodes, then 2 atomics per lane of warp 0
    sred[tid] = make_float2(r0, r1);
    __syncthreads();
    if (wrp == 0) {
        float2 s = sred[lane];
        #pragma unroll
        for (int w = 1; w < 8; w++) {
            float2 t = sred[w * 32 + lane];
            s.x += t.x; s.y += t.y;
        }
        atomicAdd(&gsum[2 * lane],     s.x);
        atomicAdd(&gsum[2 * lane + 1], s.y);
    }
}

// ---------------- tail ----------------

// per-sheet: gather+mean, geo MLP, fusion, q head.  Block (64 threads) per sheet.
__global__ void tail_kernel(const float* __restrict__ H, const int* __restrict__ idx,
                            const float* __restrict__ sheet_feat,
                            const float* __restrict__ geoW1, const float* __restrict__ geob1,
                            const float* __restrict__ geoW2, const float* __restrict__ geob2,
                            const float* __restrict__ fusW,  const float* __restrict__ fusb,
                            const float* __restrict__ qW1,   const float* __restrict__ qb1,
                            const float* __restrict__ qW2,   const float* __restrict__ qb2,
                            const float* __restrict__ gsum, float inv_n,
                            float* __restrict__ out) {
    __shared__ float sf[FEAT], t1[HID], geo[HID], se[HID], fused[HID], g[HID];
    __shared__ float red[2];
    int s = blockIdx.x, j = threadIdx.x;

    {
        const int* row = idx + s * SHEET_LEN;
        float acc = 0.f;
        #pragma unroll 4
        for (int r = 0; r < SHEET_LEN; r++) {
            int node = row[r];               // warp-uniform
            acc += H[(size_t)node * HID + j];
        }
        se[j] = acc * (1.0f / SHEET_LEN);
    }
    if (j < FEAT) sf[j] = sheet_feat[s * FEAT + j];
    g[j] = gsum[j] * inv_n;
    __syncthreads();

    float a = geob1[j];
    #pragma unroll
    for (int k = 0; k < FEAT; k++) a = fmaf(sf[k], geoW1[k * HID + j], a);
    t1[j] = fmaxf(a, 0.f);
    __syncthreads();

    a = geob2[j];
    #pragma unroll 8
    for (int k = 0; k < HID; k++) a = fmaf(t1[k], geoW2[k * HID + j], a);
    geo[j] = a;
    __syncthreads();

    a = fusb[j];
    #pragma unroll 8
    for (int k = 0; k < HID; k++) a = fmaf(se[k],  fusW[k * HID + j], a);
    #pragma unroll 8
    for (int k = 0; k < HID; k++) a = fmaf(geo[k], fusW[(HID + k) * HID + j], a);
    fused[j] = fmaxf(a, 0.f);
    __syncthreads();

    a = qb1[j];
    #pragma unroll 8
    for (int k = 0; k < HID; k++) a = fmaf(fused[k], qW1[k * HID + j], a);
    #pragma unroll 8
    for (int k = 0; k < HID; k++) a = fmaf(g[k],     qW1[(HID + k) * HID + j], a);
    float q = fmaxf(a, 0.f) * qW2[j];

    #pragma unroll
    for (int off = 16; off; off >>= 1) q += __shfl_down_sync(0xffffffffu, q, off);
    if ((j & 31) == 0) red[j >> 5] = q;
    __syncthreads();
    if (j == 0) out[s] = red[0] + red[1] + qb2[0];
}

// ---------------- launch ----------------

extern "C" void kernel_launch(void* const* d_in, const int* in_sizes, int n_in,
                              void* d_out, int out_size) {
    const float* x          = (const float*)d_in[0];
    const int*   ei         = (const int*)d_in[1];   // [2, E], int32
    const int*   sheet_idx  = (const int*)d_in[3];
    const float* sheet_feat = (const float*)d_in[4];
    const float* W1 = (const float*)d_in[5];  const float* b1 = (const float*)d_in[6];
    const float* W2 = (const float*)d_in[7];  const float* b2 = (const float*)d_in[8];
    const float* W3 = (const float*)d_in[9];  const float* b3 = (const float*)d_in[10];
    const float* gW1 = (const float*)d_in[11]; const float* gb1 = (const float*)d_in[12];
    const float* gW2 = (const float*)d_in[13]; const float* gb2 = (const float*)d_in[14];
    const float* fW  = (const float*)d_in[15]; const float* fb  = (const float*)d_in[16];
    const float* qW1 = (const float*)d_in[17]; const float* qb1 = (const float*)d_in[18];
    const float* qW2 = (const float*)d_in[19]; const float* qb2 = (const float*)d_in[20];
    float* out = (float*)d_out;

    const int* src = ei;
    const int* dst = ei + N_EDGES;

    float *hB, *dinv, *gsum;
    int *deg, *rowptr, *rowcur, *part;
    int2 *csr;
    __half2 *g2, *g3;
    cudaGetSymbolAddress((void**)&hB, d_hB);
    cudaGetSymbolAddress((void**)&deg, d_deg);
    cudaGetSymbolAddress((void**)&dinv, d_dinv);
    cudaGetSymbolAddress((void**)&rowptr, d_rowptr);
    cudaGetSymbolAddress((void**)&rowcur, d_rowcur);
    cudaGetSymbolAddress((void**)&csr, d_csr);
    cudaGetSymbolAddress((void**)&part, d_part);
    cudaGetSymbolAddress((void**)&gsum, d_gsum);
    cudaGetSymbolAddress((void**)&g2, d_g2);
    cudaGetSymbolAddress((void**)&g3, d_g3);

    // --- CSR build ---
    zero_kernel<<<(N_NODES + 255) / 256, 256>>>(deg, gsum, N_NODES);
    deg_kernel<<<(N_EDGES + 255) / 256, 256>>>(dst, deg, N_EDGES);
    scan1_kernel<<<SCAN_GRID, SCAN_BLK>>>(deg, dinv, part, N_NODES);
    scan3_kernel<<<SCAN_GRID, SCAN_BLK>>>(deg, part, rowptr, rowcur, N_NODES);
    scatter_kernel<<<(N_EDGES + 255) / 256, 256>>>(src, dst, dinv, rowcur, csr, N_EDGES);

    const int agg_grid = (N_NODES * 32 + 255) / 256;   // warp per node

    // A: agg(x) -> gemm1 -> relu -> gemm2  (fp16 out)
    layerA_kernel<<<agg_grid, 256>>>(x, rowptr, csr, dinv, W1, b1, W2, g2, N_NODES);
    // B: agg(g2) -> +b2,relu -> gemm3  (fp16 out)
    layerB_kernel<<<agg_grid, 256>>>(g2, rowptr, csr, dinv, b2, W3, g3, N_NODES);
    // C: agg(g3) -> +b3,relu -> fp32 rows + fused gsum
    layerC_kernel<<<agg_grid, 256>>>(g3, rowptr, csr, dinv, b3, (float2*)hB, gsum, N_NODES);

    // tail
    tail_kernel<<<N_SHEETS, HID>>>(hB, sheet_idx, sheet_feat,
                                   gW1, gb1, gW2, gb2, fW, fb, qW1, qb1, qW2, qb2,
                                   gsum, 1.0f / N_NODES, out);
}

// round 16
// speedup vs baseline: 1.1501x; 1.1501x over previous
#include <cuda_runtime.h>
#include <cuda_bf16.h>
#include <cuda_fp16.h>

#define N_NODES 50000
#define N_EDGES 800000
#define FEAT 10
#define HID 64
#define N_SHEETS 256
#define SHEET_LEN 128

#define SCAN_BLK 512
#define SCAN_GRID ((N_NODES + SCAN_BLK - 1) / SCAN_BLK)   // 98

// ---------------- scratch (static device globals; no allocation) ----------------
__device__ __align__(16) float d_hA[N_NODES * HID];   // fp16 gemm outputs live here (cast)
__device__ __align__(16) float d_hB[N_NODES * HID];   // fp32 agg outputs / gemm inputs
__device__ int   d_deg[N_NODES];
__device__ float d_dinv[N_NODES];
__device__ int   d_rowptr[N_NODES + 1];
__device__ int   d_rowcur[N_NODES];
__device__ __align__(16) int2 d_csr[N_EDGES];         // {src, weight-as-int}
__device__ int   d_part[SCAN_GRID + 32];
__device__ float d_gsum[HID];

// ---------------- CSR build ----------------

__global__ void zero_kernel(int* deg, float* gsum, int n) {
    int i = blockIdx.x * blockDim.x + threadIdx.x;
    if (i < n) deg[i] = 0;
    if (i < HID) gsum[i] = 0.f;
}

__global__ void deg_kernel(const int* __restrict__ dst, int* __restrict__ deg, int nE) {
    int e = blockIdx.x * blockDim.x + threadIdx.x;
    if (e < nE) atomicAdd(&deg[dst[e]], 1);
}

// pass 1: per-block sums of deg, plus dinv (reads deg anyway)
__global__ void scan1_kernel(const int* __restrict__ deg, float* __restrict__ dinv,
                             int* __restrict__ partials, int n) {
    __shared__ int ws[SCAN_BLK / 32];
    int i = blockIdx.x * blockDim.x + threadIdx.x;
    int lane = threadIdx.x & 31, wrp = threadIdx.x >> 5;
    int v = (i < n) ? deg[i] : 0;
    if (i < n) dinv[i] = rsqrtf((float)v + 1.0f);
    int s = v;
    #pragma unroll
    for (int off = 16; off; off >>= 1) s += __shfl_down_sync(0xffffffffu, s, off);
    if (lane == 0) ws[wrp] = s;
    __syncthreads();
    if (wrp == 0) {
        int t = (lane < SCAN_BLK / 32) ? ws[lane] : 0;
        #pragma unroll
        for (int off = 16; off; off >>= 1) t += __shfl_down_sync(0xffffffffu, t, off);
        if (lane == 0) partials[blockIdx.x] = t;
    }
}

// pass 2 (merged): per-block rescan; warp 1 concurrently sums partials[0..bid-1]
__global__ void scan3_kernel(const int* __restrict__ deg, const int* __restrict__ partials,
                             int* __restrict__ row_ptr, int* __restrict__ row_cur, int n) {
    __shared__ int ws[SCAN_BLK / 32];
    __shared__ int s_base;
    int i = blockIdx.x * blockDim.x + threadIdx.x;
    int lane = threadIdx.x & 31, wrp = threadIdx.x >> 5;
    int v = (i < n) ? deg[i] : 0;
    int x = v;
    #pragma unroll
    for (int off = 1; off < 32; off <<= 1) {
        int y = __shfl_up_sync(0xffffffffu, x, off);
        if (lane >= off) x += y;
    }
    if (lane == 31) ws[wrp] = x;
    __syncthreads();
    if (wrp == 0) {
        int y = (lane < SCAN_BLK / 32) ? ws[lane] : 0;
        #pragma unroll
        for (int off = 1; off < 16; off <<= 1) {
            int z = __shfl_up_sync(0xffffffffu, y, off);
            if (lane >= off) y += z;
        }
        if (lane < SCAN_BLK / 32) ws[lane] = y;
    } else if (wrp == 1) {
        int pre = 0;
        for (int bp = 0; bp < SCAN_GRID; bp += 32) {
            int idx = bp + lane;
            int pv = (idx < SCAN_GRID && idx < blockIdx.x) ? partials[idx] : 0;
            #pragma unroll
            for (int off = 16; off; off >>= 1) pv += __shfl_down_sync(0xffffffffu, pv, off);
            if (lane == 0) pre += pv;
        }
        if (lane == 0) s_base = pre;
    }
    __syncthreads();
    int excl = x - v + (wrp > 0 ? ws[wrp - 1] : 0) + s_base;
    if (i < n) { row_ptr[i] = excl; row_cur[i] = excl; }
    if (i == n - 1) row_ptr[n] = excl + v;
}

// scatter with fused edge weight, packed {src, w}
__global__ void scatter_kernel(const int* __restrict__ src, const int* __restrict__ dst,
                               const float* __restrict__ dinv,
                               int* __restrict__ rowcur, int2* __restrict__ csr, int nE) {
    int e = blockIdx.x * blockDim.x + threadIdx.x;
    if (e >= nE) return;
    int d = dst[e];
    int s = src[e];
    int p = atomicAdd(&rowcur[d], 1);
    csr[p] = make_int2(s, __float_as_int(dinv[s] * dinv[d]));
}

// ---------------- layer kernels (R9 structure: separate agg / gemm) ----------------

// layer-1 pre-agg on raw features (A·X), 10-wide.
__global__ void aggx_kernel(const float* __restrict__ X, const int* __restrict__ row_ptr,
                            const int2* __restrict__ csr, const float* __restrict__ dinv,
                            float* __restrict__ out, int n) {
    int warp = (blockIdx.x * blockDim.x + threadIdx.x) >> 5;
    int lane = threadIdx.x & 31;
    if (warp >= n) return;
    int beg = row_ptr[warp];
    int end = row_ptr[warp + 1];
    float acc = 0.f;
    for (int e = beg; e < end; e++) {
        int2 sw = csr[e];                  // warp-uniform 8B load
        float w = __int_as_float(sw.y);
        if (lane < FEAT)
            acc = fmaf(w, X[(size_t)sw.x * FEAT + lane], acc);
    }
    if (lane < FEAT) {
        float di = dinv[warp];
        float xv = X[(size_t)warp * FEAT + lane];
        out[(size_t)warp * FEAT + lane] = fmaf(di * di, xv, acc);
    }
}

// fused gemm1+gemm2:  G = relu(T0 @ W1 + b1) @ W2   (T0 10-wide), output fp16
__global__ void __launch_bounds__(128)
gemm12_kernel(const float* __restrict__ T0, const float* __restrict__ W1,
              const float* __restrict__ b1, const float* __restrict__ W2,
              __half* __restrict__ Hout, int n) {
    __shared__ __align__(16) float W1sm[FEAT * HID];
    __shared__ __align__(16) float W2sm[HID * HID];
    __shared__ float b1sm[HID];
    int tid = threadIdx.x;
    for (int i = tid; i < FEAT * HID; i += 128) W1sm[i] = W1[i];
    for (int i = tid; i < HID * HID; i += 128) W2sm[i] = W2[i];
    if (tid < HID) b1sm[tid] = b1[tid];
    __syncthreads();
    int node = blockIdx.x * 128 + tid;
    if (node >= n) return;

    float xv[FEAT];
    {
        const float2* xr = (const float2*)(T0 + (size_t)node * FEAT);
        #pragma unroll
        for (int i = 0; i < FEAT / 2; i++) {
            float2 v = xr[i];
            xv[2 * i] = v.x; xv[2 * i + 1] = v.y;
        }
    }
    float h[HID];
    #pragma unroll
    for (int j = 0; j < HID; j++) h[j] = b1sm[j];
    #pragma unroll
    for (int k = 0; k < FEAT; k++) {
        const float4* wr = (const float4*)&W1sm[k * HID];
        #pragma unroll
        for (int j = 0; j < 16; j++) {
            float4 w = wr[j];
            h[4*j+0] = fmaf(xv[k], w.x, h[4*j+0]);
            h[4*j+1] = fmaf(xv[k], w.y, h[4*j+1]);
            h[4*j+2] = fmaf(xv[k], w.z, h[4*j+2]);
            h[4*j+3] = fmaf(xv[k], w.w, h[4*j+3]);
        }
    }
    #pragma unroll
    for (int j = 0; j < HID; j++) h[j] = fmaxf(h[j], 0.f);

    float g[HID];
    #pragma unroll
    for (int j = 0; j < HID; j++) g[j] = 0.f;
    #pragma unroll
    for (int k = 0; k < HID; k++) {
        float hv = h[k];
        const float4* wr = (const float4*)&W2sm[k * HID];
        #pragma unroll
        for (int j = 0; j < 16; j++) {
            float4 w = wr[j];
            g[4*j+0] = fmaf(hv, w.x, g[4*j+0]);
            g[4*j+1] = fmaf(hv, w.y, g[4*j+1]);
            g[4*j+2] = fmaf(hv, w.z, g[4*j+2]);
            g[4*j+3] = fmaf(hv, w.w, g[4*j+3]);
        }
    }
    __half2 hh[HID / 2];
    #pragma unroll
    for (int i = 0; i < HID / 2; i++)
        hh[i] = __floats2half2_rn(g[2 * i], g[2 * i + 1]);
    uint4* orow = (uint4*)(Hout + (size_t)node * HID);
    const uint4* hr = (const uint4*)hh;
    #pragma unroll
    for (int i = 0; i < 8; i++) orow[i] = hr[i];
}

// gemm3:  G = X @ W3  (64-wide fp32 in), output fp16, no bias/relu (done in agg)
__global__ void __launch_bounds__(128)
gemm_kernel(const float* __restrict__ X, const float* __restrict__ W,
            __half* __restrict__ Hout, int n) {
    __shared__ __align__(16) float Wsm[HID * HID];
    int tid = threadIdx.x;
    for (int i = tid; i < HID * HID; i += 128) Wsm[i] = W[i];
    __syncthreads();
    int node = blockIdx.x * 128 + tid;
    if (node >= n) return;

    float xv[HID];
    {
        const float4* xr = (const float4*)(X + (size_t)node * HID);
        #pragma unroll
        for (int i = 0; i < 16; i++) {
            float4 v = xr[i];
            xv[4*i] = v.x; xv[4*i+1] = v.y; xv[4*i+2] = v.z; xv[4*i+3] = v.w;
        }
    }
    float g[HID];
    #pragma unroll
    for (int j = 0; j < HID; j++) g[j] = 0.f;
    #pragma unroll
    for (int k = 0; k < HID; k++) {
        float hv = xv[k];
        const float4* wr = (const float4*)&Wsm[k * HID];
        #pragma unroll
        for (int j = 0; j < 16; j++) {
            float4 w = wr[j];
            g[4*j+0] = fmaf(hv, w.x, g[4*j+0]);
            g[4*j+1] = fmaf(hv, w.y, g[4*j+1]);
            g[4*j+2] = fmaf(hv, w.z, g[4*j+2]);
            g[4*j+3] = fmaf(hv, w.w, g[4*j+3]);
        }
    }
    __half2 hh[HID / 2];
    #pragma unroll
    for (int i = 0; i < HID / 2; i++)
        hh[i] = __floats2half2_rn(g[2 * i], g[2 * i + 1]);
    uint4* orow = (uint4*)(Hout + (size_t)node * HID);
    const uint4* hr = (const uint4*)hh;
    #pragma unroll
    for (int i = 0; i < 8; i++) orow[i] = hr[i];
}

// agg on fp16 rows: out = relu(sum_e w_e*h_src + di^2*h_i + b).  Warp per node.
// GSUM: fuse global-mean partial sums via block reduce + per-feature atomics.
template <bool GSUM>
__global__ void __launch_bounds__(256)
agg16_kernel(const __half2* __restrict__ H2, const int* __restrict__ row_ptr,
             const int2* __restrict__ csr, const float* __restrict__ dinv,
             const float* __restrict__ b,
             float* __restrict__ out, float* __restrict__ gsum, int n) {
    __shared__ float2 sred[GSUM ? 256 : 1];
    int tid  = threadIdx.x;
    int warp = (blockIdx.x * blockDim.x + tid) >> 5;
    int lane = tid & 31;

    float r0 = 0.f, r1 = 0.f;
    if (warp < n) {
        int beg = row_ptr[warp];
        int end = row_ptr[warp + 1];
        float a0 = 0.f, a1 = 0.f;
        for (int e = beg; e < end; e++) {
            int2 sw = csr[e];                  // warp-uniform 8B load
            float w = __int_as_float(sw.y);
            float2 f = __half22float2(H2[(size_t)sw.x * 32 + lane]);   // 128B coalesced
            a0 = fmaf(w, f.x, a0);
            a1 = fmaf(w, f.y, a1);
        }
        float di = dinv[warp];
        float d2 = di * di;
        float2 fs = __half22float2(H2[(size_t)warp * 32 + lane]);
        float2 bb = ((const float2*)b)[lane];
        r0 = fmaxf(fmaf(d2, fs.x, a0) + bb.x, 0.f);
        r1 = fmaxf(fmaf(d2, fs.y, a1) + bb.y, 0.f);
        ((float2*)out)[(size_t)warp * 32 + lane] = make_float2(r0, r1);
    }

    if (GSUM) {
        sred[tid] = make_float2(r0, r1);
        __syncthreads();
        if (tid < 32) {
            float2 s = sred[lane];
            #pragma unroll
            for (int w = 1; w < 8; w++) {
                float2 t = sred[w * 32 + lane];
                s.x += t.x; s.y += t.y;
            }
            atomicAdd(&gsum[2 * lane],     s.x);
            atomicAdd(&gsum[2 * lane + 1], s.y);
        }
    }
}

// ---------------- tail ----------------

// per-sheet: gather+mean, geo MLP, fusion, q head.  Block (64 threads) per sheet.
__global__ void tail_kernel(const float* __restrict__ H, const int* __restrict__ idx,
                            const float* __restrict__ sheet_feat,
                            const float* __restrict__ geoW1, const float* __restrict__ geob1,
                            const float* __restrict__ geoW2, const float* __restrict__ geob2,
                            const float* __restrict__ fusW,  const float* __restrict__ fusb,
                            const float* __restrict__ qW1,   const float* __restrict__ qb1,
                            const float* __restrict__ qW2,   const float* __restrict__ qb2,
                            const float* __restrict__ gsum, float inv_n,
                            float* __restrict__ out) {
    __shared__ float sf[FEAT], t1[HID], geo[HID], se[HID], fused[HID], g[HID];
    __shared__ float red[2];
    int s = blockIdx.x, j = threadIdx.x;

    {
        const int* row = idx + s * SHEET_LEN;
        float acc = 0.f;
        #pragma unroll 4
        for (int r = 0; r < SHEET_LEN; r++) {
            int node = row[r];               // warp-uniform
            acc += H[(size_t)node * HID + j];
        }
        se[j] = acc * (1.0f / SHEET_LEN);
    }
    if (j < FEAT) sf[j] = sheet_feat[s * FEAT + j];
    g[j] = gsum[j] * inv_n;
    __syncthreads();

    float a = geob1[j];
    #pragma unroll
    for (int k = 0; k < FEAT; k++) a = fmaf(sf[k], geoW1[k * HID + j], a);
    t1[j] = fmaxf(a, 0.f);
    __syncthreads();

    a = geob2[j];
    #pragma unroll 8
    for (int k = 0; k < HID; k++) a = fmaf(t1[k], geoW2[k * HID + j], a);
    geo[j] = a;
    __syncthreads();

    a = fusb[j];
    #pragma unroll 8
    for (int k = 0; k < HID; k++) a = fmaf(se[k],  fusW[k * HID + j], a);
    #pragma unroll 8
    for (int k = 0; k < HID; k++) a = fmaf(geo[k], fusW[(HID + k) * HID + j], a);
    fused[j] = fmaxf(a, 0.f);
    __syncthreads();

    a = qb1[j];
    #pragma unroll 8
    for (int k = 0; k < HID; k++) a = fmaf(fused[k], qW1[k * HID + j], a);
    #pragma unroll 8
    for (int k = 0; k < HID; k++) a = fmaf(g[k],     qW1[(HID + k) * HID + j], a);
    float q = fmaxf(a, 0.f) * qW2[j];

    #pragma unroll
    for (int off = 16; off; off >>= 1) q += __shfl_down_sync(0xffffffffu, q, off);
    if ((j & 31) == 0) red[j >> 5] = q;
    __syncthreads();
    if (j == 0) out[s] = red[0] + red[1] + qb2[0];
}

// ---------------- launch ----------------

extern "C" void kernel_launch(void* const* d_in, const int* in_sizes, int n_in,
                              void* d_out, int out_size) {
    const float* x          = (const float*)d_in[0];
    const int*   ei         = (const int*)d_in[1];   // [2, E], int32
    const int*   sheet_idx  = (const int*)d_in[3];
    const float* sheet_feat = (const float*)d_in[4];
    const float* W1 = (const float*)d_in[5];  const float* b1 = (const float*)d_in[6];
    const float* W2 = (const float*)d_in[7];  const float* b2 = (const float*)d_in[8];
    const float* W3 = (const float*)d_in[9];  const float* b3 = (const float*)d_in[10];
    const float* gW1 = (const float*)d_in[11]; const float* gb1 = (const float*)d_in[12];
    const float* gW2 = (const float*)d_in[13]; const float* gb2 = (const float*)d_in[14];
    const float* fW  = (const float*)d_in[15]; const float* fb  = (const float*)d_in[16];
    const float* qW1 = (const float*)d_in[17]; const float* qb1 = (const float*)d_in[18];
    const float* qW2 = (const float*)d_in[19]; const float* qb2 = (const float*)d_in[20];
    float* out = (float*)d_out;

    const int* src = ei;
    const int* dst = ei + N_EDGES;

    float *hA, *hB, *dinv, *gsum;
    int *deg, *rowptr, *rowcur, *part;
    int2 *csr;
    cudaGetSymbolAddress((void**)&hA, d_hA);
    cudaGetSymbolAddress((void**)&hB, d_hB);
    cudaGetSymbolAddress((void**)&deg, d_deg);
    cudaGetSymbolAddress((void**)&dinv, d_dinv);
    cudaGetSymbolAddress((void**)&rowptr, d_rowptr);
    cudaGetSymbolAddress((void**)&rowcur, d_rowcur);
    cudaGetSymbolAddress((void**)&csr, d_csr);
    cudaGetSymbolAddress((void**)&part, d_part);
    cudaGetSymbolAddress((void**)&gsum, d_gsum);

    __half* hA16 = (__half*)hA;
    __half2* hA2 = (__half2*)hA;

    // --- CSR build (merged scan) ---
    zero_kernel<<<(N_NODES + 255) / 256, 256>>>(deg, gsum, N_NODES);
    deg_kernel<<<(N_EDGES + 255) / 256, 256>>>(dst, deg, N_EDGES);
    scan1_kernel<<<SCAN_GRID, SCAN_BLK>>>(deg, dinv, part, N_NODES);
    scan3_kernel<<<SCAN_GRID, SCAN_BLK>>>(deg, part, rowptr, rowcur, N_NODES);
    scatter_kernel<<<(N_EDGES + 255) / 256, 256>>>(src, dst, dinv, rowcur, csr, N_EDGES);

    const int gemm_grid = (N_NODES + 127) / 128;
    const int agg_grid  = (N_NODES * 32 + 255) / 256;

    // layer 1+2 front half:  t0 = agg(x);  g2 = relu(t0·W1+b1)·W2  (fp16 out)
    aggx_kernel<<<agg_grid, 256>>>(x, rowptr, csr, dinv, hB, N_NODES);
    gemm12_kernel<<<gemm_grid, 128>>>(hB, W1, b1, W2, hA16, N_NODES);
    // layer 2 aggregation: h2 = relu(agg(g2)+b2)   (fp32 out)
    agg16_kernel<false><<<agg_grid, 256>>>(hA2, rowptr, csr, dinv, b2, hB, nullptr, N_NODES);
    // layer 3: g3 = h2·W3 (fp16), h3 = relu(agg(g3)+b3) (fp32) + fused gsum
    gemm_kernel<<<gemm_grid, 128>>>(hB, W3, hA16, N_NODES);
    agg16_kernel<true><<<agg_grid, 256>>>(hA2, rowptr, csr, dinv, b3, hB, gsum, N_NODES);

    // tail
    tail_kernel<<<N_SHEETS, HID>>>(hB, sheet_idx, sheet_feat,
                                   gW1, gb1, gW2, gb2, fW, fb, qW1, qb1, qW2, qb2,
                                   gsum, 1.0f / N_NODES, out);
}